// round 1
// baseline (speedup 1.0000x reference)
#include <cuda_runtime.h>

#define IMG_H 512
#define IMG_W 512
#define OUT_H 502
#define OUT_W 502
#define N_IMG 48            // 16 * 3
#define N_PIX (N_IMG * IMG_H * IMG_W)      // 12,582,912
#define N_OUT_D 12096192.0  // 48 * 502 * 502
#define TX 32
#define TY 32
#define TILE_IN 42          // TX + 10 halo

// Gaussian window (size 11, sigma 1.5), normalized — matches reference to ~1e-7.
__constant__ float c_w[11] = {
    0.00102837f, 0.00759869f, 0.03600077f, 0.10936070f, 0.21300560f,
    0.26601173f,
    0.21300560f, 0.10936070f, 0.03600077f, 0.00759869f, 0.00102837f
};

__device__ unsigned int gMaxKey;
__device__ unsigned int gMinKey;
__device__ double gSum;

// Monotone float <-> uint mapping (handles negatives correctly).
__device__ __forceinline__ unsigned int fkey(float f) {
    unsigned int u = __float_as_uint(f);
    return (u & 0x80000000u) ? ~u : (u | 0x80000000u);
}
__device__ __forceinline__ float funkey(unsigned int u) {
    return __uint_as_float((u & 0x80000000u) ? (u ^ 0x80000000u) : ~u);
}

__global__ void k_init() {
    gMaxKey = 0u;
    gMinKey = 0xFFFFFFFFu;
    gSum = 0.0;
}

__global__ __launch_bounds__(256) void k_minmax(const float* __restrict__ x, int n) {
    float vmin = 3.4e38f, vmax = -3.4e38f;
    int idx = blockIdx.x * blockDim.x + threadIdx.x;
    int stride = gridDim.x * blockDim.x;
    int n4 = n >> 2;
    const float4* x4 = (const float4*)x;
    for (int i = idx; i < n4; i += stride) {
        float4 v = x4[i];
        vmin = fminf(vmin, fminf(fminf(v.x, v.y), fminf(v.z, v.w)));
        vmax = fmaxf(vmax, fmaxf(fmaxf(v.x, v.y), fmaxf(v.z, v.w)));
    }
    for (int i = (n4 << 2) + idx; i < n; i += stride) {
        float v = x[i];
        vmin = fminf(vmin, v);
        vmax = fmaxf(vmax, v);
    }
    #pragma unroll
    for (int o = 16; o; o >>= 1) {
        vmin = fminf(vmin, __shfl_xor_sync(0xffffffffu, vmin, o));
        vmax = fmaxf(vmax, __shfl_xor_sync(0xffffffffu, vmax, o));
    }
    __shared__ float smin[8], smax[8];
    int lane = threadIdx.x & 31, wid = threadIdx.x >> 5;
    if (lane == 0) { smin[wid] = vmin; smax[wid] = vmax; }
    __syncthreads();
    if (threadIdx.x == 0) {
        float bmin = smin[0], bmax = smax[0];
        #pragma unroll
        for (int i = 1; i < 8; i++) {
            bmin = fminf(bmin, smin[i]);
            bmax = fmaxf(bmax, smax[i]);
        }
        atomicMax(&gMaxKey, fkey(bmax));
        atomicMin(&gMinKey, fkey(bmin));
    }
}

__global__ __launch_bounds__(256) void k_ssim(const float* __restrict__ P,
                                              const float* __restrict__ T) {
    __shared__ float sp[TILE_IN][TILE_IN + 1];
    __shared__ float st[TILE_IN][TILE_IN + 1];
    __shared__ float h[5][TILE_IN][TX + 1];
    __shared__ float wsum[8];

    const int img = blockIdx.z;
    const int ox0 = blockIdx.x * TX;
    const int oy0 = blockIdx.y * TY;
    const float* __restrict__ p = P + (size_t)img * IMG_H * IMG_W;
    const float* __restrict__ t = T + (size_t)img * IMG_H * IMG_W;
    const int tid = threadIdx.x;

    // ---- load 42x42 halo tile (zero-fill out of range; only happens on edge tiles) ----
    for (int i = tid; i < TILE_IN * TILE_IN; i += 256) {
        int r = i / TILE_IN, c = i - r * TILE_IN;
        int gr = oy0 + r, gc = ox0 + c;
        float vp = 0.f, vt = 0.f;
        if (gr < IMG_H && gc < IMG_W) {
            size_t off = (size_t)gr * IMG_W + gc;
            vp = p[off];
            vt = t[off];
        }
        sp[r][c] = vp;
        st[r][c] = vt;
    }
    __syncthreads();

    // ---- horizontal 11-tap pass for the 5 quantities ----
    for (int i = tid; i < TILE_IN * TX; i += 256) {
        int r = i >> 5, c = i & 31;
        float a0 = 0.f, a1 = 0.f, a2 = 0.f, a3 = 0.f, a4 = 0.f;
        #pragma unroll
        for (int j = 0; j < 11; j++) {
            float w = c_w[j];
            float vp = sp[r][c + j];
            float vt = st[r][c + j];
            float wp = w * vp;
            float wt = w * vt;
            a0 += wp;
            a1 += wt;
            a2 = fmaf(wp, vp, a2);
            a3 = fmaf(wt, vt, a3);
            a4 = fmaf(wp, vt, a4);
        }
        h[0][r][c] = a0;
        h[1][r][c] = a1;
        h[2][r][c] = a2;
        h[3][r][c] = a3;
        h[4][r][c] = a4;
    }
    __syncthreads();

    // ---- vertical pass + SSIM map + partial sum ----
    const float L = funkey(gMaxKey) - funkey(gMinKey);
    const float C1 = (0.01f * L) * (0.01f * L);
    const float C2 = (0.03f * L) * (0.03f * L);

    const int tx = tid & 31, ty = tid >> 5;
    float localsum = 0.f;
    #pragma unroll
    for (int k = 0; k < 4; k++) {
        int r = ty + (k << 3);          // output row within tile, 0..31
        int oy = oy0 + r, ox = ox0 + tx;
        if (oy < OUT_H && ox < OUT_W) {
            float m1 = 0.f, m2 = 0.f, e11 = 0.f, e22 = 0.f, e12 = 0.f;
            #pragma unroll
            for (int i = 0; i < 11; i++) {
                float w = c_w[i];
                m1  = fmaf(w, h[0][r + i][tx], m1);
                m2  = fmaf(w, h[1][r + i][tx], m2);
                e11 = fmaf(w, h[2][r + i][tx], e11);
                e22 = fmaf(w, h[3][r + i][tx], e22);
                e12 = fmaf(w, h[4][r + i][tx], e12);
            }
            float mu1s = m1 * m1;
            float mu2s = m2 * m2;
            float mu12 = m1 * m2;
            float s1 = e11 - mu1s;
            float s2 = e22 - mu2s;
            float s12 = e12 - mu12;
            float v1 = 2.f * s12 + C2;
            float v2 = s1 + s2 + C2;
            float num = (2.f * mu12 + C1) * v1;
            float den = (mu1s + mu2s + C1) * v2;
            localsum += num / den;
        }
    }

    // ---- block reduce, double atomic accumulate ----
    #pragma unroll
    for (int o = 16; o; o >>= 1)
        localsum += __shfl_xor_sync(0xffffffffu, localsum, o);
    if ((tid & 31) == 0) wsum[tid >> 5] = localsum;
    __syncthreads();
    if (tid == 0) {
        float s = 0.f;
        #pragma unroll
        for (int i = 0; i < 8; i++) s += wsum[i];
        atomicAdd(&gSum, (double)s);
    }
}

__global__ void k_final(float* out) {
    out[0] = (float)(-gSum / N_OUT_D);
}

extern "C" void kernel_launch(void* const* d_in, const int* in_sizes, int n_in,
                              void* d_out, int out_size) {
    const float* y_pred = (const float*)d_in[0];
    const float* y_true = (const float*)d_in[1];
    float* out = (float*)d_out;

    k_init<<<1, 1>>>();
    k_minmax<<<1024, 256>>>(y_pred, N_PIX);
    dim3 grid((OUT_W + TX - 1) / TX, (OUT_H + TY - 1) / TY, N_IMG);
    k_ssim<<<grid, 256>>>(y_pred, y_true);
    k_final<<<1, 1>>>(out);
}

// round 2
// speedup vs baseline: 1.0645x; 1.0645x over previous
#include <cuda_runtime.h>

#define IMG_H 512
#define IMG_W 512
#define OUT_H 502
#define OUT_W 502
#define N_IMG 48            // 16 * 3
#define N_PIX (N_IMG * IMG_H * IMG_W)
#define N_OUT_D 12096192.0  // 48 * 502 * 502
#define TX 32
#define TY 32
#define TILE_IN 42          // TX + 10 halo
#define GRID_X 16
#define GRID_Y 16
#define TOTAL_BLOCKS (GRID_X * GRID_Y * N_IMG)

// Device globals: statically initialized; the LAST k_ssim block resets them
// to these exact values so every graph replay starts clean.
__device__ double gSum = 0.0;
__device__ unsigned int gCount = 0u;
__device__ unsigned int gMaxKey = 0u;
__device__ unsigned int gMinKey = 0xFFFFFFFFu;

// Monotone float <-> uint mapping (handles negatives correctly).
__device__ __forceinline__ unsigned int fkey(float f) {
    unsigned int u = __float_as_uint(f);
    return (u & 0x80000000u) ? ~u : (u | 0x80000000u);
}
__device__ __forceinline__ float funkey(unsigned int u) {
    return __uint_as_float((u & 0x80000000u) ? (u ^ 0x80000000u) : ~u);
}

__global__ __launch_bounds__(256) void k_minmax(const float* __restrict__ x, int n) {
    float vmin = 3.4e38f, vmax = -3.4e38f;
    int idx = blockIdx.x * blockDim.x + threadIdx.x;
    int stride = gridDim.x * blockDim.x;
    int n4 = n >> 2;
    const float4* x4 = (const float4*)x;
    for (int i = idx; i < n4; i += stride) {
        float4 v = x4[i];
        vmin = fminf(vmin, fminf(fminf(v.x, v.y), fminf(v.z, v.w)));
        vmax = fmaxf(vmax, fmaxf(fmaxf(v.x, v.y), fmaxf(v.z, v.w)));
    }
    for (int i = (n4 << 2) + idx; i < n; i += stride) {
        float v = x[i];
        vmin = fminf(vmin, v);
        vmax = fmaxf(vmax, v);
    }
    #pragma unroll
    for (int o = 16; o; o >>= 1) {
        vmin = fminf(vmin, __shfl_xor_sync(0xffffffffu, vmin, o));
        vmax = fmaxf(vmax, __shfl_xor_sync(0xffffffffu, vmax, o));
    }
    __shared__ float smin[8], smax[8];
    int lane = threadIdx.x & 31, wid = threadIdx.x >> 5;
    if (lane == 0) { smin[wid] = vmin; smax[wid] = vmax; }
    __syncthreads();
    if (threadIdx.x == 0) {
        float bmin = smin[0], bmax = smax[0];
        #pragma unroll
        for (int i = 1; i < 8; i++) {
            bmin = fminf(bmin, smin[i]);
            bmax = fmaxf(bmax, smax[i]);
        }
        atomicMax(&gMaxKey, fkey(bmax));
        atomicMin(&gMinKey, fkey(bmin));
    }
}

__global__ __launch_bounds__(256) void k_ssim(const float* __restrict__ P,
                                              const float* __restrict__ T,
                                              float* __restrict__ out) {
    // Compile-time weights -> FFMA-imm (rt_SMSP=1, 2x throughput of 3-reg FFMA)
    constexpr float W[11] = {
        0.00102837f, 0.00759869f, 0.03600077f, 0.10936070f, 0.21300560f,
        0.26601173f,
        0.21300560f, 0.10936070f, 0.03600077f, 0.00759869f, 0.00102837f
    };

    __shared__ float sp[TILE_IN][TILE_IN + 1];
    __shared__ float st[TILE_IN][TILE_IN + 1];
    __shared__ float h[5][TILE_IN][TX + 1];
    __shared__ float wsum[8];

    const int img = blockIdx.z;
    const int ox0 = blockIdx.x * TX;
    const int oy0 = blockIdx.y * TY;
    const float* __restrict__ p = P + (size_t)img * IMG_H * IMG_W;
    const float* __restrict__ t = T + (size_t)img * IMG_H * IMG_W;
    const int tid = threadIdx.x;
    const int tx = tid & 31, ty = tid >> 5;

    // ---- load 42x42 halo tile (zero-fill out of range) ----
    for (int r = ty; r < TILE_IN; r += 8) {
        int gr = oy0 + r;
        #pragma unroll
        for (int cb = 0; cb < TILE_IN; cb += 32) {
            int c = cb + tx;
            if (c < TILE_IN) {
                int gc = ox0 + c;
                float vp = 0.f, vt = 0.f;
                if (gr < IMG_H && gc < IMG_W) {
                    size_t off = (size_t)gr * IMG_W + gc;
                    vp = p[off];
                    vt = t[off];
                }
                sp[r][c] = vp;
                st[r][c] = vt;
            }
        }
    }
    __syncthreads();

    // ---- horizontal 11-tap pass, 4 output columns per work item ----
    for (int i = tid; i < TILE_IN * 8; i += 256) {
        int r = i >> 3;
        int c0 = (i & 7) << 2;
        float a0[4] = {0.f, 0.f, 0.f, 0.f};
        float a1[4] = {0.f, 0.f, 0.f, 0.f};
        float a2[4] = {0.f, 0.f, 0.f, 0.f};
        float a3[4] = {0.f, 0.f, 0.f, 0.f};
        float a4[4] = {0.f, 0.f, 0.f, 0.f};
        #pragma unroll
        for (int j = 0; j < 14; j++) {
            float vp = sp[r][c0 + j];
            float vt = st[r][c0 + j];
            float pp = vp * vp;
            float tt = vt * vt;
            float pt = vp * vt;
            #pragma unroll
            for (int u = 0; u < 4; u++) {
                int k = j - u;
                if (k >= 0 && k < 11) {
                    a0[u] = fmaf(vp, W[k], a0[u]);
                    a1[u] = fmaf(vt, W[k], a1[u]);
                    a2[u] = fmaf(pp, W[k], a2[u]);
                    a3[u] = fmaf(tt, W[k], a3[u]);
                    a4[u] = fmaf(pt, W[k], a4[u]);
                }
            }
        }
        #pragma unroll
        for (int u = 0; u < 4; u++) {
            h[0][r][c0 + u] = a0[u];
            h[1][r][c0 + u] = a1[u];
            h[2][r][c0 + u] = a2[u];
            h[3][r][c0 + u] = a3[u];
            h[4][r][c0 + u] = a4[u];
        }
    }
    __syncthreads();

    // ---- vertical 11-tap pass, 4 output rows per thread ----
    const float L = funkey(gMaxKey) - funkey(gMinKey);
    const float C1 = (0.01f * L) * (0.01f * L);
    const float C2 = (0.03f * L) * (0.03f * L);

    const int r0 = ty << 2;   // rows r0..r0+3
    float m1[4]  = {0.f, 0.f, 0.f, 0.f};
    float m2[4]  = {0.f, 0.f, 0.f, 0.f};
    float e11[4] = {0.f, 0.f, 0.f, 0.f};
    float e22[4] = {0.f, 0.f, 0.f, 0.f};
    float e12[4] = {0.f, 0.f, 0.f, 0.f};
    #pragma unroll
    for (int i = 0; i < 14; i++) {
        float q0 = h[0][r0 + i][tx];
        float q1 = h[1][r0 + i][tx];
        float q2 = h[2][r0 + i][tx];
        float q3 = h[3][r0 + i][tx];
        float q4 = h[4][r0 + i][tx];
        #pragma unroll
        for (int u = 0; u < 4; u++) {
            int k = i - u;
            if (k >= 0 && k < 11) {
                m1[u]  = fmaf(q0, W[k], m1[u]);
                m2[u]  = fmaf(q1, W[k], m2[u]);
                e11[u] = fmaf(q2, W[k], e11[u]);
                e22[u] = fmaf(q3, W[k], e22[u]);
                e12[u] = fmaf(q4, W[k], e12[u]);
            }
        }
    }

    float localsum = 0.f;
    const int ox = ox0 + tx;
    #pragma unroll
    for (int u = 0; u < 4; u++) {
        int oy = oy0 + r0 + u;
        if (oy < OUT_H && ox < OUT_W) {
            float mu1s = m1[u] * m1[u];
            float mu2s = m2[u] * m2[u];
            float mu12 = m1[u] * m2[u];
            float s1 = e11[u] - mu1s;
            float s2 = e22[u] - mu2s;
            float s12 = e12[u] - mu12;
            float v1 = 2.f * s12 + C2;
            float v2 = s1 + s2 + C2;
            float num = (2.f * mu12 + C1) * v1;
            float den = (mu1s + mu2s + C1) * v2;
            localsum += __fdividef(num, den);
        }
    }

    // ---- block reduce, double atomic accumulate, last block finalizes ----
    #pragma unroll
    for (int o = 16; o; o >>= 1)
        localsum += __shfl_xor_sync(0xffffffffu, localsum, o);
    if ((tid & 31) == 0) wsum[tid >> 5] = localsum;
    __syncthreads();
    if (tid == 0) {
        float s = 0.f;
        #pragma unroll
        for (int i = 0; i < 8; i++) s += wsum[i];
        atomicAdd(&gSum, (double)s);
        __threadfence();
        unsigned int old = atomicAdd(&gCount, 1u);
        if (old == TOTAL_BLOCKS - 1) {
            double v = atomicAdd(&gSum, 0.0);   // coherent read via L2
            out[0] = (float)(-v / N_OUT_D);
            // reset for next graph replay
            gSum = 0.0;
            gCount = 0u;
            gMaxKey = 0u;
            gMinKey = 0xFFFFFFFFu;
        }
    }
}

extern "C" void kernel_launch(void* const* d_in, const int* in_sizes, int n_in,
                              void* d_out, int out_size) {
    const float* y_pred = (const float*)d_in[0];
    const float* y_true = (const float*)d_in[1];
    float* out = (float*)d_out;

    k_minmax<<<1024, 256>>>(y_pred, N_PIX);
    dim3 grid(GRID_X, GRID_Y, N_IMG);
    k_ssim<<<grid, 256>>>(y_pred, y_true, out);
}

// round 3
// speedup vs baseline: 1.3377x; 1.2566x over previous
#include <cuda_runtime.h>

#define IMG_H 512
#define IMG_W 512
#define OUT_H 502
#define OUT_W 502
#define N_IMG 48
#define N_PIX (N_IMG * IMG_H * IMG_W)
#define N_OUT_D 12096192.0
#define TX 32
#define TY 22
#define IN_ROWS 32          // TY + 10
#define SP_W 44             // padded input-tile width (42 used), 16B-aligned rows
#define H_W 36              // padded h width (32 used), 16B-aligned rows
#define H_ROWS 34           // 32 + 2 zero pad rows for the tail warp
#define GRID_X 16
#define GRID_Y 23           // ceil(502/22)
#define TOTAL_BLOCKS (GRID_X * GRID_Y * N_IMG)   // 17664

__device__ double gSum = 0.0;
__device__ unsigned int gCount = 0u;
__device__ unsigned int gMaxKey = 0u;
__device__ unsigned int gMinKey = 0xFFFFFFFFu;

__device__ __forceinline__ unsigned int fkey(float f) {
    unsigned int u = __float_as_uint(f);
    return (u & 0x80000000u) ? ~u : (u | 0x80000000u);
}
__device__ __forceinline__ float funkey(unsigned int u) {
    return __uint_as_float((u & 0x80000000u) ? (u ^ 0x80000000u) : ~u);
}

__global__ __launch_bounds__(256) void k_minmax(const float* __restrict__ x, int n) {
    float vmin = 3.4e38f, vmax = -3.4e38f;
    int idx = blockIdx.x * blockDim.x + threadIdx.x;
    int stride = gridDim.x * blockDim.x;
    int n4 = n >> 2;
    const float4* x4 = (const float4*)x;
    for (int i = idx; i < n4; i += stride) {
        float4 v = x4[i];
        vmin = fminf(vmin, fminf(fminf(v.x, v.y), fminf(v.z, v.w)));
        vmax = fmaxf(vmax, fmaxf(fmaxf(v.x, v.y), fmaxf(v.z, v.w)));
    }
    #pragma unroll
    for (int o = 16; o; o >>= 1) {
        vmin = fminf(vmin, __shfl_xor_sync(0xffffffffu, vmin, o));
        vmax = fmaxf(vmax, __shfl_xor_sync(0xffffffffu, vmax, o));
    }
    __shared__ float smin[8], smax[8];
    int lane = threadIdx.x & 31, wid = threadIdx.x >> 5;
    if (lane == 0) { smin[wid] = vmin; smax[wid] = vmax; }
    __syncthreads();
    if (threadIdx.x == 0) {
        float bmin = smin[0], bmax = smax[0];
        #pragma unroll
        for (int i = 1; i < 8; i++) {
            bmin = fminf(bmin, smin[i]);
            bmax = fmaxf(bmax, smax[i]);
        }
        atomicMax(&gMaxKey, fkey(bmax));
        atomicMin(&gMinKey, fkey(bmin));
    }
}

__global__ __launch_bounds__(256, 5) void k_ssim(const float* __restrict__ P,
                                                 const float* __restrict__ T,
                                                 float* __restrict__ out) {
    constexpr float W[11] = {
        0.00102837f, 0.00759869f, 0.03600077f, 0.10936070f, 0.21300560f,
        0.26601173f,
        0.21300560f, 0.10936070f, 0.03600077f, 0.00759869f, 0.00102837f
    };

    __shared__ float sp[IN_ROWS][SP_W];
    __shared__ float st[IN_ROWS][SP_W];
    __shared__ float h[5][H_ROWS][H_W];
    __shared__ float wsum[8];

    const int img = blockIdx.z;
    const int ox0 = blockIdx.x * TX;
    const int oy0 = blockIdx.y * TY;
    const float* __restrict__ p = P + (size_t)img * IMG_H * IMG_W;
    const float* __restrict__ t = T + (size_t)img * IMG_H * IMG_W;
    const int tid = threadIdx.x;
    const int tx = tid & 31, ty8 = tid >> 5;

    // ---- load 42x32 halo tile (zero-fill out of range) ----
    #pragma unroll
    for (int r = 0; r < 4; r++) {
        int row = ty8 + (r << 3);               // ty8 + {0,8,16,24}
        int gr = oy0 + row;
        bool rok = gr < IMG_H;
        size_t base = (size_t)gr * IMG_W;
        {   // cols 0..31
            int gc = ox0 + tx;
            bool ok = rok && gc < IMG_W;
            sp[row][tx] = ok ? p[base + gc] : 0.f;
            st[row][tx] = ok ? t[base + gc] : 0.f;
        }
        if (tx < 10) {   // cols 32..41
            int gc = ox0 + 32 + tx;
            bool ok = rok && gc < IMG_W;
            sp[row][32 + tx] = ok ? p[base + gc] : 0.f;
            st[row][32 + tx] = ok ? t[base + gc] : 0.f;
        }
    }
    // zero the two h pad rows (read by tail warp, masked from sum)
    for (int i = tid; i < 5 * 2 * H_W; i += 256) {
        int q = i / (2 * H_W);
        int rem = i - q * (2 * H_W);
        h[q][IN_ROWS + rem / H_W][rem % H_W] = 0.f;
    }
    __syncthreads();

    // ---- horizontal 11-tap pass: exactly one 4-col group per thread ----
    {
        const int r = tid >> 3;
        const int c0 = (tid & 7) << 2;
        float a0[4] = {0.f, 0.f, 0.f, 0.f};
        float a1[4] = {0.f, 0.f, 0.f, 0.f};
        float a2[4] = {0.f, 0.f, 0.f, 0.f};
        float a3[4] = {0.f, 0.f, 0.f, 0.f};
        float a4[4] = {0.f, 0.f, 0.f, 0.f};
        const float4* sp4 = reinterpret_cast<const float4*>(&sp[r][c0]);
        const float4* st4 = reinterpret_cast<const float4*>(&st[r][c0]);
        #pragma unroll
        for (int ch = 0; ch < 4; ch++) {
            float4 qp = sp4[ch];
            float4 qt = st4[ch];
            float vpc[4] = {qp.x, qp.y, qp.z, qp.w};
            float vtc[4] = {qt.x, qt.y, qt.z, qt.w};
            #pragma unroll
            for (int jv = 0; jv < 4; jv++) {
                const int j = (ch << 2) + jv;
                if (j < 14) {
                    float vp = vpc[jv], vt = vtc[jv];
                    float pp = vp * vp;
                    float tt = vt * vt;
                    float pt = vp * vt;
                    #pragma unroll
                    for (int u = 0; u < 4; u++) {
                        const int k = j - u;
                        if (k >= 0 && k < 11) {
                            a0[u] = fmaf(vp, W[k], a0[u]);
                            a1[u] = fmaf(vt, W[k], a1[u]);
                            a2[u] = fmaf(pp, W[k], a2[u]);
                            a3[u] = fmaf(tt, W[k], a3[u]);
                            a4[u] = fmaf(pt, W[k], a4[u]);
                        }
                    }
                }
            }
        }
        *reinterpret_cast<float4*>(&h[0][r][c0]) = make_float4(a0[0], a0[1], a0[2], a0[3]);
        *reinterpret_cast<float4*>(&h[1][r][c0]) = make_float4(a1[0], a1[1], a1[2], a1[3]);
        *reinterpret_cast<float4*>(&h[2][r][c0]) = make_float4(a2[0], a2[1], a2[2], a2[3]);
        *reinterpret_cast<float4*>(&h[3][r][c0]) = make_float4(a3[0], a3[1], a3[2], a3[3]);
        *reinterpret_cast<float4*>(&h[4][r][c0]) = make_float4(a4[0], a4[1], a4[2], a4[3]);
    }
    __syncthreads();

    // ---- vertical 11-tap pass: 3 consecutive rows per thread ----
    const float L = funkey(gMaxKey) - funkey(gMinKey);
    const float C1 = (0.01f * L) * (0.01f * L);
    const float C2 = (0.03f * L) * (0.03f * L);

    const int r0 = ty8 * 3;                // 0,3,..,21 (ty8=7 -> rows 21..23; 22,23 masked)
    float m1[3]  = {0.f, 0.f, 0.f};
    float m2[3]  = {0.f, 0.f, 0.f};
    float e11[3] = {0.f, 0.f, 0.f};
    float e22[3] = {0.f, 0.f, 0.f};
    float e12[3] = {0.f, 0.f, 0.f};
    #pragma unroll
    for (int i = 0; i < 13; i++) {
        float q0 = h[0][r0 + i][tx];
        float q1 = h[1][r0 + i][tx];
        float q2 = h[2][r0 + i][tx];
        float q3 = h[3][r0 + i][tx];
        float q4 = h[4][r0 + i][tx];
        #pragma unroll
        for (int u = 0; u < 3; u++) {
            const int k = i - u;
            if (k >= 0 && k < 11) {
                m1[u]  = fmaf(q0, W[k], m1[u]);
                m2[u]  = fmaf(q1, W[k], m2[u]);
                e11[u] = fmaf(q2, W[k], e11[u]);
                e22[u] = fmaf(q3, W[k], e22[u]);
                e12[u] = fmaf(q4, W[k], e12[u]);
            }
        }
    }

    float localsum = 0.f;
    const int ox = ox0 + tx;
    #pragma unroll
    for (int u = 0; u < 3; u++) {
        int lr = r0 + u;
        int oy = oy0 + lr;
        if (lr < TY && oy < OUT_H && ox < OUT_W) {
            float mu1s = m1[u] * m1[u];
            float mu2s = m2[u] * m2[u];
            float mu12 = m1[u] * m2[u];
            float s1 = e11[u] - mu1s;
            float s2 = e22[u] - mu2s;
            float s12 = e12[u] - mu12;
            float v1 = 2.f * s12 + C2;
            float v2 = s1 + s2 + C2;
            float num = (2.f * mu12 + C1) * v1;
            float den = (mu1s + mu2s + C1) * v2;
            localsum += __fdividef(num, den);
        }
    }

    // ---- block reduce, double atomic accumulate, last block finalizes ----
    #pragma unroll
    for (int o = 16; o; o >>= 1)
        localsum += __shfl_xor_sync(0xffffffffu, localsum, o);
    if ((tid & 31) == 0) wsum[tid >> 5] = localsum;
    __syncthreads();
    if (tid == 0) {
        float s = 0.f;
        #pragma unroll
        for (int i = 0; i < 8; i++) s += wsum[i];
        atomicAdd(&gSum, (double)s);
        __threadfence();
        unsigned int old = atomicAdd(&gCount, 1u);
        if (old == TOTAL_BLOCKS - 1) {
            double v = atomicAdd(&gSum, 0.0);
            out[0] = (float)(-v / N_OUT_D);
            gSum = 0.0;
            gCount = 0u;
            gMaxKey = 0u;
            gMinKey = 0xFFFFFFFFu;
        }
    }
}

extern "C" void kernel_launch(void* const* d_in, const int* in_sizes, int n_in,
                              void* d_out, int out_size) {
    const float* y_pred = (const float*)d_in[0];
    const float* y_true = (const float*)d_in[1];
    float* out = (float*)d_out;

    k_minmax<<<1024, 256>>>(y_pred, N_PIX);
    dim3 grid(GRID_X, GRID_Y, N_IMG);
    k_ssim<<<grid, 256>>>(y_pred, y_true, out);
}